// round 3
// baseline (speedup 1.0000x reference)
#include <cuda_runtime.h>
#include <float.h>
#include <stdint.h>

#define MAXN 8192

// Scratch (no device allocations allowed)
__device__ int g_noleaf[MAXN];
__device__ int g_leaf[MAXN];

// ---------------------------------------------------------------------------
// Kernel 1: init scratch
__global__ void init_kernel(int n) {
    int t = blockIdx.x * blockDim.x + threadIdx.x;
    if (t < n) { g_noleaf[t] = 0; g_leaf[t] = -1; }
}

// Kernel 2: mark non-leaf nodes (any node appearing as a parent)
__global__ void scatter_kernel(const int* __restrict__ mask_index, int T) {
    int t = blockIdx.x * blockDim.x + threadIdx.x;
    if (t < T) {
        int v = mask_index[t];
        if (v >= 0 && v < MAXN) g_noleaf[v] = 1;
    }
}

// Kernel 3: ordered compaction of leaves (single block, 1024 threads, block scan)
__global__ void __launch_bounds__(1024) leaf_kernel(int n) {
    __shared__ int part[1024];
    const int tid = threadIdx.x;
    const int PER = 8;                      // 1024*8 = 8192 = MAXN
    int base = tid * PER;
    int loc[PER];
    int cnt = 0;
#pragma unroll
    for (int k = 0; k < PER; k++) {
        int j = base + k;
        loc[k] = cnt;
        int v = (j < n) ? g_noleaf[j] : 1;  // out-of-range treated as non-leaf
        cnt += v;
    }
    part[tid] = cnt;
    __syncthreads();
    // Hillis-Steele inclusive scan
    for (int off = 1; off < 1024; off <<= 1) {
        int v = (tid >= off) ? part[tid - off] : 0;
        __syncthreads();
        part[tid] += v;
        __syncthreads();
    }
    int excl = (tid > 0) ? part[tid - 1] : 0;
#pragma unroll
    for (int k = 0; k < PER; k++) {
        int j = base + k;
        if (j < n && g_noleaf[j] == 0) {
            int pos = j - (excl + loc[k]);   // = #leaves with index < j
            if (pos >= 0 && pos < n) g_leaf[pos] = j;
        }
    }
}

// Kernel 4: retrieve_indices — walk parent chain from each leaf slot
__global__ void retrieve_kernel(const int* __restrict__ mask_index,
                                const int* __restrict__ tpi,
                                float* __restrict__ outRI, int n, int depth) {
    int r = blockIdx.x * blockDim.x + threadIdx.x;
    if (r >= n) return;
    int cur = g_leaf[r];
    long long base = (long long)r * depth;
    for (int d = 0; d < depth; d++) {
        int cc  = cur < 0 ? 0 : cur;
        int pos = tpi[cc];
        outRI[base + d] = (cur >= 0 && pos >= d) ? (float)cur : -1.0f;
        cur = (cur > 0) ? mask_index[cur - 1] : -1;
    }
}

// Kernel 5: the bandwidth kernel — one block per row.
// Build an n-bit ancestor bitset in shared memory, then stream float4 stores:
// tree_mask row (0/1) and masked_scores row (-FLT_MAX except at set bits,
// where we gather the few surviving score values).
__global__ void __launch_bounds__(256) mask_scores_kernel(
    const int* __restrict__ mask_index, const float* __restrict__ scores,
    float* __restrict__ outMask, float* __restrict__ outScores, int n) {
    __shared__ unsigned bits[MAXN / 32];
    const int nw = (n + 31) >> 5;
    for (int w = threadIdx.x; w < nw; w += blockDim.x) bits[w] = 0;
    __syncthreads();

    const int i = blockIdx.x;
    if (threadIdx.x == 0) {
        bits[0] |= 1u;                       // column 0 always true
        bits[i >> 5] |= 1u << (i & 31);      // diagonal
        int cur = i;
#pragma unroll 1
        for (int s = 0; s < 32 && cur > 0; s++) {   // ancestor chain (depth <= 7)
            int p = mask_index[cur - 1];
            if (p < 0 || p >= n) break;
            bits[p >> 5] |= 1u << (p & 31);
            cur = p;
        }
    }
    __syncthreads();

    const float NEG = -FLT_MAX;              // jnp.finfo(float32).min
    const long long rowOff = (long long)i * n;
    const int stride4 = blockDim.x * 4;

    int j = threadIdx.x * 4;
    for (; j + 3 < n; j += stride4) {
        unsigned b = (bits[j >> 5] >> (j & 31)) & 0xFu;  // (j&31) multiple of 4
        float4 m = make_float4(0.f, 0.f, 0.f, 0.f);
        float4 s = make_float4(NEG, NEG, NEG, NEG);
        if (b) {
            if (b & 1u) { m.x = 1.f; s.x = scores[rowOff + j];     }
            if (b & 2u) { m.y = 1.f; s.y = scores[rowOff + j + 1]; }
            if (b & 4u) { m.z = 1.f; s.z = scores[rowOff + j + 2]; }
            if (b & 8u) { m.w = 1.f; s.w = scores[rowOff + j + 3]; }
        }
        __stcs(reinterpret_cast<float4*>(outMask + rowOff + j), m);
        __stcs(reinterpret_cast<float4*>(outScores + rowOff + j), s);
    }
    // tail (n not multiple of 4*blockDim) — not hit for n=8192, kept for safety
    for (; j < n; j++) {
        unsigned on = (bits[j >> 5] >> (j & 31)) & 1u;
        outMask[rowOff + j]   = on ? 1.f : 0.f;
        outScores[rowOff + j] = on ? scores[rowOff + j] : NEG;
    }
}

// ---------------------------------------------------------------------------
extern "C" void kernel_launch(void* const* d_in, const int* in_sizes, int n_in,
                              void* d_out, int out_size) {
    // Identify inputs by element count (robust to scalar inputs / reordering):
    //   scores: n*n (largest), tpi: n, mask_index: n-1
    int scoresIdx = 0;
    long long maxSz = -1;
    for (int k = 0; k < n_in; k++)
        if ((long long)in_sizes[k] > maxSz) { maxSz = in_sizes[k]; scoresIdx = k; }
    // n = sqrt(maxSz)
    int n = 1;
    while ((long long)(n + 1) * (n + 1) <= maxSz) n++;   // n <= 8192, cheap host loop
    const int T = n - 1;

    int miIdx = -1, tpiIdx = -1;
    for (int k = 0; k < n_in; k++) {
        if (k == scoresIdx) continue;
        if (in_sizes[k] == T && miIdx < 0) miIdx = k;
        else if (in_sizes[k] == n && tpiIdx < 0) tpiIdx = k;
    }
    if (miIdx < 0) miIdx = 0;
    if (tpiIdx < 0) tpiIdx = (miIdx == 1) ? 0 : 1;

    const int*   mask_index = (const int*)d_in[miIdx];
    const int*   tpi        = (const int*)d_in[tpiIdx];
    const float* scores     = (const float*)d_in[scoresIdx];

    const long long nn = (long long)n * n;
    // out = [tree_mask (n*n) | retrieve_indices (n*depth) | masked_scores (n*n)]
    int depth = (int)(((long long)out_size - 2 * nn) / n);
    if (depth < 0) depth = 0;

    float* outMask   = (float*)d_out;
    float* outRI     = outMask + nn;
    float* outScores = outRI + (long long)n * depth;

    init_kernel<<<(n + 255) / 256, 256>>>(n);
    scatter_kernel<<<(T + 255) / 256, 256>>>(mask_index, T);
    leaf_kernel<<<1, 1024>>>(n);
    if (depth > 0)
        retrieve_kernel<<<(n + 127) / 128, 128>>>(mask_index, tpi, outRI, n, depth);
    mask_scores_kernel<<<n, 256>>>(mask_index, scores, outMask, outScores, n);
}